// round 11
// baseline (speedup 1.0000x reference)
#include <cuda_runtime.h>
#include <math.h>

// Problem constants (fixed by the reference: B=8192, V=8, J=32)
constexpr int BB = 8192;
constexpr int VV = 8;
constexpr int JJ = 32;
constexpr int PAIRS = BB * VV;                        // 65536 (b,v) problems
constexpr int WARPS_PER_BLOCK = 8;
constexpr int PAIRS_PER_WARP = 4;                     // 8-lane segments (best measured config)
constexpr int PAIRS_PER_BLOCK = WARPS_PER_BLOCK * PAIRS_PER_WARP;  // 32
constexpr int NBLOCKS = PAIRS / PAIRS_PER_BLOCK;      // 2048
constexpr float SCALE_KPS = 0.1f;
constexpr float THRESHOLD = 100.0f;
constexpr float ALPHA = 0.1f;
constexpr float T_BETA = 63.095734448019324f;         // 100^0.9
constexpr double FIX = 262144.0;                      // 2^18 fixed-point scale

__device__ unsigned long long g_accum = 0ull;         // fixed-point grid sum
__device__ unsigned int g_ticket = 0u;                // completion counter

// single-MUFU approximate ops
__device__ __forceinline__ float frcp_fast(float x) {
    float r; asm("rcp.approx.f32 %0, %1;" : "=f"(r) : "f"(x)); return r;
}
__device__ __forceinline__ float fsqrt_fast(float x) {
    float r; asm("sqrt.approx.f32 %0, %1;" : "=f"(r) : "f"(x)); return r;
}
// branchless x^0.1 via lg2/ex2
__device__ __forceinline__ float pow01_fast(float x) {
    float l; asm("lg2.approx.f32 %0, %1;" : "=f"(l) : "f"(x));
    float r; asm("ex2.approx.f32 %0, %1;" : "=f"(r) : "f"(l * ALPHA));
    return r;
}

struct Acc { float pn2, in2, ls; };

// projection with precomposed M = K @ cam: 9 FMA + rcp per joint (short chain)
__device__ __forceinline__ void do_joint(
    float X, float Y, float Z, float ix, float iy,
    const float* __restrict__ M, Acc& a)
{
    const float px = M[0] * X + M[1] * Y + M[2]  * Z + M[3];
    const float py = M[4] * X + M[5] * Y + M[6]  * Z + M[7];
    const float pz = M[8] * X + M[9] * Y + M[10] * Z + M[11];
    const float iz = frcp_fast(pz);
    const float u = px * iz, w = py * iz;
    a.pn2 += u * u + w * w;
    a.in2 += ix * ix + iy * iy;
    float d0 = (u - ix) * SCALE_KPS; d0 = d0 * d0;
    float d1 = (w - iy) * SCALE_KPS; d1 = d1 * d1;
    // branchless select: most lanes exceed THRESHOLD anyway
    const float o0 = pow01_fast(d0) * T_BETA;
    const float o1 = pow01_fast(d1) * T_BETA;
    d0 = (d0 > THRESHOLD) ? o0 : d0;
    d1 = (d1 > THRESHOLD) ? o1 : d1;
    a.ls += d0 + d1;
}

__global__ __launch_bounds__(WARPS_PER_BLOCK * 32, 7)   // cap regs<=36 -> 56 warps/SM
void qpl_fused(const float* __restrict__ Kmat,
               const float* __restrict__ cam,
               const float* __restrict__ kps,
               const float* __restrict__ init,
               float* __restrict__ out) {
    const int t = threadIdx.x;
    const int warp = t >> 5;
    const int lane = t & 31;
    const int grp = lane >> 3;      // which of 4 pairs in this warp
    const int sub = lane & 7;       // lane in 8-lane group; handles joints 4*sub..4*sub+3
    const int pair = blockIdx.x * PAIRS_PER_BLOCK + warp * PAIRS_PER_WARP + grp;
    const int b = pair >> 3;        // 4 consecutive pairs share one batch

    // ---- loads: 16B-aligned vectors / group-uniform broadcast ----
    const float4* ikp = reinterpret_cast<const float4*>(init) + (size_t)pair * 16 + sub * 2;
    const float4 ia = ikp[0], ib = ikp[1];
    const float4* kp4 = reinterpret_cast<const float4*>(kps + (size_t)b * (JJ * 3) + sub * 12);
    const float4 q0 = kp4[0], q1 = kp4[1], q2 = kp4[2];
    const float4* C = reinterpret_cast<const float4*>(cam + (size_t)pair * 12);
    const float4 c0 = C[0], c1 = C[1], c2 = C[2];
    const float* Kp = Kmat + (size_t)pair * 9;

    // ---- M = K @ cam (3x4): 36 FMA with wide ILP; K+cam die after this ----
    float M[12];
    {
        const float k0 = Kp[0], k1 = Kp[1], k2 = Kp[2];
        const float k3 = Kp[3], k4 = Kp[4], k5 = Kp[5];
        const float k6 = Kp[6], k7 = Kp[7], k8 = Kp[8];
        const float r0[4] = {c0.x, c0.y, c0.z, c0.w};
        const float r1[4] = {c1.x, c1.y, c1.z, c1.w};
        const float r2[4] = {c2.x, c2.y, c2.z, c2.w};
#pragma unroll
        for (int j = 0; j < 4; j++) {
            M[j]     = k0 * r0[j] + k1 * r1[j] + k2 * r2[j];
            M[4 + j] = k3 * r0[j] + k4 * r1[j] + k5 * r2[j];
            M[8 + j] = k6 * r0[j] + k7 * r1[j] + k8 * r2[j];
        }
    }

    Acc a = {0.0f, 0.0f, 0.0f};
    // 4 independent short joint chains -> ILP hides MUFU latency
    do_joint(q0.x, q0.y, q0.z, ia.x, ia.y, M, a);
    do_joint(q0.w, q1.x, q1.y, ia.z, ia.w, M, a);
    do_joint(q1.z, q1.w, q2.x, ib.x, ib.y, M, a);
    do_joint(q2.y, q2.z, q2.w, ib.z, ib.w, M, a);

    // ---- segmented butterfly reduce within each 8-lane group ----
#pragma unroll
    for (int o = 4; o; o >>= 1) {
        a.pn2 += __shfl_xor_sync(0xFFFFFFFFu, a.pn2, o);
        a.in2 += __shfl_xor_sync(0xFFFFFFFFu, a.in2, o);
        a.ls  += __shfl_xor_sync(0xFFFFFFFFu, a.ls,  o);
    }

    __shared__ float sm[PAIRS_PER_BLOCK];
    if (sub == 0) {
        const float penal = fabsf(fsqrt_fast(a.pn2 * frcp_fast(a.in2)) - 1.0f);
        sm[warp * PAIRS_PER_WARP + grp] = penal * a.ls * 0.5f;
    }
    __syncthreads();

    // warp 0 reduces the 32 per-pair results
    if (warp == 0) {
        float s = sm[lane];
#pragma unroll
        for (int o = 16; o; o >>= 1) s += __shfl_xor_sync(0xFFFFFFFFu, s, o);
        if (lane == 0) {
            // order-invariant integer accumulation => deterministic grid sum
            const long long q = __double2ll_rn((double)s * FIX);
            atomicAdd(&g_accum, (unsigned long long)q);
            __threadfence();
            const unsigned int tk = atomicAdd(&g_ticket, 1u);
            if (tk == (unsigned int)(NBLOCKS - 1)) {
                const unsigned long long total = atomicAdd(&g_accum, 0ull);
                const double mean = ((double)(long long)total) / FIX / (double)PAIRS;
                out[0] = (float)mean;
                atomicExch(&g_accum, 0ull);
                __threadfence();
                atomicExch(&g_ticket, 0u);
            }
        }
    }
}

extern "C" void kernel_launch(void* const* d_in, const int* in_sizes, int n_in,
                              void* d_out, int out_size) {
    const float* Kmat = (const float*)d_in[0];  // [B,V,3,3]
    const float* cam  = (const float*)d_in[1];  // [B,V,3,4]
    const float* kps  = (const float*)d_in[2];  // [B,J,3]
    const float* init = (const float*)d_in[3];  // [B,V,J,2]
    float* out = (float*)d_out;

    qpl_fused<<<NBLOCKS, WARPS_PER_BLOCK * 32>>>(Kmat, cam, kps, init, out);
}